// round 1
// baseline (speedup 1.0000x reference)
#include <cuda_runtime.h>
#include <math.h>

// Problem constants
#define HID    256
#define BS     64
#define DCS    16
#define NCLS   60
#define QSZ    5
#define TOPK   5
#define TOPKQ  100
#define NROWS  (BS * DCS)          // 1024
#define NKEYS  (NCLS * DCS)        // 960
#define CAND   (TOPK * QSZ * DCS)  // 400
#define CPB    (QSZ * DCS)         // 80 rows per class in raw queue_key

// ---------------------------------------------------------------------------
// Scratch (no allocations allowed -> __device__ globals)
// ---------------------------------------------------------------------------
// layout: KEY(960*256) QRY(1024*256) QQ(1024*256) QHAT(1024*256)
//         SC1(1024*960) CAT(1024*512) QSUM(1024*256)
#define OFF_KEY   0
#define OFF_QRY   (OFF_KEY  + NKEYS*HID)
#define OFF_QQ    (OFF_QRY  + NROWS*HID)
#define OFF_QHAT  (OFF_QQ   + NROWS*HID)
#define OFF_SC1   (OFF_QHAT + NROWS*HID)
#define OFF_CAT   (OFF_SC1  + NROWS*NKEYS)
#define OFF_QSUM  (OFF_CAT  + NROWS*2*HID)
#define SCRATCH_F (OFF_QSUM + NROWS*HID)

__device__ float g_scratch[SCRATCH_F];
__device__ int   g_topc[NROWS * TOPK];

// ---------------------------------------------------------------------------
// Generic tiled SGEMM with optional bias.
//   BT = true : C[M,N] = A[M,K] * B[N,K]^T + bias      (torch Linear)
//   BT = false: C[M,N] = A[M,K] * B[K,N]   + bias
// BM=BN=64, BK=16, 256 threads, 4x4 per thread. M,N multiples of 64,
// K multiple of 16.
// ---------------------------------------------------------------------------
template <bool BT>
__global__ void gemm_bias_kernel(const float* __restrict__ A,
                                 const float* __restrict__ B,
                                 const float* __restrict__ bias,
                                 float* __restrict__ C,
                                 int M, int N, int K,
                                 int lda, int ldb, int ldc)
{
    __shared__ float As[16][64];
    __shared__ float Bs[16][64];

    const int tid = threadIdx.x;
    const int tx  = tid & 15;   // 0..15
    const int ty  = tid >> 4;   // 0..15
    const int bm  = blockIdx.y * 64;
    const int bn  = blockIdx.x * 64;

    float acc[4][4] = {};

    for (int k0 = 0; k0 < K; k0 += 16) {
        // A tile: As[k][m]
#pragma unroll
        for (int r = 0; r < 4; r++) {
            int m = ty + 16 * r;
            As[tx][m] = A[(size_t)(bm + m) * lda + k0 + tx];
        }
        if (BT) {
            // B is [N x K]
#pragma unroll
            for (int r = 0; r < 4; r++) {
                int n = ty + 16 * r;
                Bs[tx][n] = B[(size_t)(bn + n) * ldb + k0 + tx];
            }
        } else {
            // B is [K x N]; vectorized coalesced load
            const float4 v = *reinterpret_cast<const float4*>(
                &B[(size_t)(k0 + ty) * ldb + bn + tx * 4]);
            Bs[ty][tx * 4 + 0] = v.x;
            Bs[ty][tx * 4 + 1] = v.y;
            Bs[ty][tx * 4 + 2] = v.z;
            Bs[ty][tx * 4 + 3] = v.w;
        }
        __syncthreads();

#pragma unroll
        for (int kk = 0; kk < 16; kk++) {
            float a[4], b[4];
#pragma unroll
            for (int i = 0; i < 4; i++) a[i] = As[kk][ty * 4 + i];
#pragma unroll
            for (int j = 0; j < 4; j++) b[j] = Bs[kk][tx * 4 + j];
#pragma unroll
            for (int i = 0; i < 4; i++)
#pragma unroll
                for (int j = 0; j < 4; j++)
                    acc[i][j] = fmaf(a[i], b[j], acc[i][j]);
        }
        __syncthreads();
    }

    float4 bb = make_float4(0.f, 0.f, 0.f, 0.f);
    if (bias) bb = *reinterpret_cast<const float4*>(&bias[bn + tx * 4]);

#pragma unroll
    for (int i = 0; i < 4; i++) {
        int m = bm + ty * 4 + i;
        float4 v;
        v.x = acc[i][0] + bb.x;
        v.y = acc[i][1] + bb.y;
        v.z = acc[i][2] + bb.z;
        v.w = acc[i][3] + bb.w;
        *reinterpret_cast<float4*>(&C[(size_t)m * ldc + bn + tx * 4]) = v;
    }
}

// ---------------------------------------------------------------------------
// Level-1: per row, top-5 of 960 scores, softmax, memory_z into CAT[:,256:512],
// and class indices for level-2.
// One block (256 threads) per row.
// ---------------------------------------------------------------------------
__global__ void topk1_kernel(const float* __restrict__ scores,
                             const float* __restrict__ keyT,
                             int* __restrict__ topc,
                             float* __restrict__ cat)
{
    __shared__ float s[NKEYS];
    __shared__ float rv[256];
    __shared__ int   ri[256];
    __shared__ float w[TOPK];
    __shared__ int   idx[TOPK];

    const int n = blockIdx.x, tid = threadIdx.x;

    for (int i = tid; i < NKEYS; i += 256) s[i] = scores[(size_t)n * NKEYS + i];
    __syncthreads();

    for (int j = 0; j < TOPK; j++) {
        float bv = -INFINITY; int bi = 0x7fffffff;
        for (int i = tid; i < NKEYS; i += 256) {
            float v = s[i];
            if (v > bv) { bv = v; bi = i; }
        }
        rv[tid] = bv; ri[tid] = bi;
        __syncthreads();
        for (int off = 128; off > 0; off >>= 1) {
            if (tid < off) {
                float ov = rv[tid + off]; int oi = ri[tid + off];
                if (ov > rv[tid] || (ov == rv[tid] && oi < ri[tid])) {
                    rv[tid] = ov; ri[tid] = oi;
                }
            }
            __syncthreads();
        }
        if (tid == 0) {
            idx[j] = ri[0];
            w[j]   = rv[0];
            s[ri[0]] = -INFINITY;
        }
        __syncthreads();
    }

    if (tid == 0) {
        float mx = w[0];
        float den = 0.f;
#pragma unroll
        for (int j = 0; j < TOPK; j++) { w[j] = expf(w[j] - mx); den += w[j]; }
        float dinv = 1.f / den;
#pragma unroll
        for (int j = 0; j < TOPK; j++) {
            w[j] *= dinv;
            topc[n * TOPK + j] = idx[j] / DCS;
        }
    }
    __syncthreads();

    // memory_z (one dim per thread) -> CAT columns [256, 512)
    float acc = 0.f;
#pragma unroll
    for (int j = 0; j < TOPK; j++)
        acc = fmaf(w[j], keyT[(size_t)idx[j] * HID + tid], acc);
    cat[(size_t)n * (2 * HID) + HID + tid] = acc;
}

// ---------------------------------------------------------------------------
// Level-2: per row, score 400 RAW queue_key candidates with qhat,
// top-100 via bitonic threshold, softmax, weighted raw-sum -> QSUM.
// One block (256 threads) per row.
// ---------------------------------------------------------------------------
__global__ void level2_kernel(const float* __restrict__ qhat,
                              const int* __restrict__ topc,
                              const float* __restrict__ rawq,
                              float* __restrict__ qsum)
{
    __shared__ float qh[HID];
    __shared__ int   cls80[TOPK];
    __shared__ float sc[CAND];
    __shared__ float sb[512];
    __shared__ int   selrow[TOPKQ];
    __shared__ float selw[TOPKQ];
    __shared__ float fred[256];
    __shared__ int   ired[256];
    __shared__ float s_den;
    __shared__ int   s_cnt;

    const int n = blockIdx.x, tid = threadIdx.x;

    qh[tid] = qhat[(size_t)n * HID + tid];
    if (tid < TOPK) cls80[tid] = topc[n * TOPK + tid] * CPB;
    if (tid == 0) s_cnt = 0;
    __syncthreads();

    // ---- scores against raw queue_key ----
#pragma unroll
    for (int mm = 0; mm < 2; mm++) {
        int m = tid + mm * 256;
        if (m < CAND) {
            int row = cls80[m / CPB] + (m % CPB);
            const float4* p  = reinterpret_cast<const float4*>(rawq + (size_t)row * HID);
            const float4* q4 = reinterpret_cast<const float4*>(qh);
            float a0 = 0.f, a1 = 0.f, a2 = 0.f, a3 = 0.f;
#pragma unroll
            for (int i = 0; i < HID / 4; i++) {
                float4 x = p[i], y = q4[i];
                a0 = fmaf(x.x, y.x, a0); a1 = fmaf(x.y, y.y, a1);
                a2 = fmaf(x.z, y.z, a2); a3 = fmaf(x.w, y.w, a3);
            }
            sc[m] = (a0 + a1) + (a2 + a3);
        }
    }
    __syncthreads();

    // ---- bitonic sort (ascending) of a value copy, padded to 512 ----
    sb[tid]       = sc[tid];
    sb[tid + 256] = (tid + 256 < CAND) ? sc[tid + 256] : -INFINITY;
    __syncthreads();
    for (int k = 2; k <= 512; k <<= 1) {
        for (int j = k >> 1; j > 0; j >>= 1) {
#pragma unroll
            for (int t = 0; t < 2; t++) {
                int i = tid + t * 256;
                int ixj = i ^ j;
                if (ixj > i) {
                    float a = sb[i], b = sb[ixj];
                    if ((a > b) == ((i & k) == 0)) { sb[i] = b; sb[ixj] = a; }
                }
            }
            __syncthreads();
        }
    }
    const float T  = sb[512 - TOPKQ];  // 100th-largest value
    const float mx = sb[511];          // max

    // ---- softmax denominator with exact-tie multiplicity ----
    {
        int   cnt = 0; float den = 0.f;
#pragma unroll
        for (int mm = 0; mm < 2; mm++) {
            int m = tid + mm * 256;
            if (m < CAND && sc[m] > T) { cnt++; den += expf(sc[m] - mx); }
        }
        fred[tid] = den; ired[tid] = cnt;
    }
    __syncthreads();
    for (int off = 128; off > 0; off >>= 1) {
        if (tid < off) { fred[tid] += fred[tid + off]; ired[tid] += ired[tid + off]; }
        __syncthreads();
    }
    if (tid == 0) {
        int G = ired[0];                       // strictly-greater count (<= 99)
        s_den = fred[0] + (float)(TOPKQ - G) * expf(T - mx);
    }
    __syncthreads();
    const float dinv = 1.f / s_den;

    // ---- build selection list: all > T, then fill with == T up to 100 ----
#pragma unroll
    for (int mm = 0; mm < 2; mm++) {
        int m = tid + mm * 256;
        if (m < CAND && sc[m] > T) {
            int p = atomicAdd(&s_cnt, 1);
            selrow[p] = cls80[m / CPB] + (m % CPB);
            selw[p]   = expf(sc[m] - mx) * dinv;
        }
    }
    __syncthreads();
#pragma unroll
    for (int mm = 0; mm < 2; mm++) {
        int m = tid + mm * 256;
        if (m < CAND && sc[m] == T) {
            int p = atomicAdd(&s_cnt, 1);
            if (p < TOPKQ) {
                selrow[p] = cls80[m / CPB] + (m % CPB);
                selw[p]   = expf(T - mx) * dinv;
            }
        }
    }
    __syncthreads();

    // ---- weighted sum of selected raw rows (thread = dim, coalesced) ----
    float acc0 = 0.f, acc1 = 0.f, acc2 = 0.f, acc3 = 0.f;
    for (int p = 0; p < TOPKQ; p += 4) {
        acc0 = fmaf(selw[p + 0], rawq[(size_t)selrow[p + 0] * HID + tid], acc0);
        acc1 = fmaf(selw[p + 1], rawq[(size_t)selrow[p + 1] * HID + tid], acc1);
        acc2 = fmaf(selw[p + 2], rawq[(size_t)selrow[p + 2] * HID + tid], acc2);
        acc3 = fmaf(selw[p + 3], rawq[(size_t)selrow[p + 3] * HID + tid], acc3);
    }
    qsum[(size_t)n * HID + tid] = (acc0 + acc1) + (acc2 + acc3);
}

// ---------------------------------------------------------------------------
// Host launcher
// ---------------------------------------------------------------------------
extern "C" void kernel_launch(void* const* d_in, const int* in_sizes, int n_in,
                              void* d_out, int out_size)
{
    // canonical input order:
    // 0:h 1:labels 2:tag 3:memory_key 4:queue_key 5:key_w 6:key_b 7:query_w
    // 8:query_b 9:kq_w 10:kq_b 11:qq_w 12:qq_b 13:proto_w 14:proto_b
    // If the scalar `tag` was dropped by the harness (n_in==14), shift >=3 down.
    const int sh = (n_in >= 15) ? 0 : 1;
    const float* h          = (const float*)d_in[0];
    const float* memory_key = (const float*)d_in[3 - sh];
    const float* queue_key  = (const float*)d_in[4 - sh];
    const float* key_w      = (const float*)d_in[5 - sh];
    const float* key_b      = (const float*)d_in[6 - sh];
    const float* query_w    = (const float*)d_in[7 - sh];
    const float* query_b    = (const float*)d_in[8 - sh];
    const float* kq_w       = (const float*)d_in[9 - sh];
    const float* kq_b       = (const float*)d_in[10 - sh];
    const float* qq_w       = (const float*)d_in[11 - sh];
    const float* qq_b       = (const float*)d_in[12 - sh];
    const float* proto_w    = (const float*)d_in[13 - sh];
    const float* proto_b    = (const float*)d_in[14 - sh];
    float* out = (float*)d_out;

    void* sp = nullptr;  cudaGetSymbolAddress(&sp, g_scratch);
    void* tp = nullptr;  cudaGetSymbolAddress(&tp, g_topc);
    float* S    = (float*)sp;
    int*   TOPC = (int*)tp;
    float* KEY  = S + OFF_KEY;
    float* QRY  = S + OFF_QRY;
    float* QQ   = S + OFF_QQ;
    float* QHAT = S + OFF_QHAT;
    float* SC1  = S + OFF_SC1;
    float* CAT  = S + OFF_CAT;
    float* QSUM = S + OFF_QSUM;

    dim3 blk(256);

    // Projections
    gemm_bias_kernel<true ><<<dim3(HID/64, NKEYS/64), blk>>>(
        memory_key, key_w, key_b, KEY, NKEYS, HID, HID, HID, HID, HID);
    gemm_bias_kernel<true ><<<dim3(HID/64, NROWS/64), blk>>>(
        h, query_w, query_b, QRY, NROWS, HID, HID, HID, HID, HID);
    gemm_bias_kernel<true ><<<dim3(HID/64, NROWS/64), blk>>>(
        h, qq_w, qq_b, QQ, NROWS, HID, HID, HID, HID, HID);
    // qhat = QQ @ kq_w  (no transpose, no bias; per-row constant is softmax/topk invariant)
    gemm_bias_kernel<false><<<dim3(HID/64, NROWS/64), blk>>>(
        QQ, kq_w, nullptr, QHAT, NROWS, HID, HID, HID, HID, HID);

    // Level-1 scores: (1024 x 960) = QRY @ KEY^T
    gemm_bias_kernel<true ><<<dim3(NKEYS/64, NROWS/64), blk>>>(
        QRY, KEY, nullptr, SC1, NROWS, NKEYS, HID, HID, HID, NKEYS);

    // Level-1 top-5 + softmax + memory_z (-> CAT[:,256:512]) + class ids
    topk1_kernel<<<NROWS, 256>>>(SC1, KEY, TOPC, CAT);

    // Level-2 scoring/top-100/weighted raw sum
    level2_kernel<<<NROWS, 256>>>(QHAT, TOPC, queue_key, QSUM);

    // queue = QSUM @ kq_w^T + kq_b  -> CAT[:,0:256]  (ldc = 512)
    gemm_bias_kernel<true ><<<dim3(HID/64, NROWS/64), blk>>>(
        QSUM, kq_w, kq_b, CAT, NROWS, HID, HID, HID, HID, 2 * HID);

    // out = CAT @ proto_w^T + proto_b   (K = 512)
    gemm_bias_kernel<true ><<<dim3(HID/64, NROWS/64), blk>>>(
        CAT, proto_w, proto_b, out, NROWS, HID, 2 * HID, 2 * HID, 2 * HID, HID);
}

// round 2
// speedup vs baseline: 1.1097x; 1.1097x over previous
#include <cuda_runtime.h>
#include <math.h>

// Problem constants
#define HID    256
#define BS     64
#define DCS    16
#define NCLS   60
#define QSZ    5
#define TOPK   5
#define TOPKQ  100
#define NROWS  (BS * DCS)          // 1024
#define NKEYS  (NCLS * DCS)        // 960
#define CAND   (TOPK * QSZ * DCS)  // 400
#define CPB    (QSZ * DCS)         // 80 rows per class in raw queue_key

// ---------------------------------------------------------------------------
// Scratch (__device__ globals; allocations are forbidden)
// ---------------------------------------------------------------------------
#define OFF_KEY   0
#define OFF_QRY   (OFF_KEY  + NKEYS*HID)
#define OFF_QHAT  (OFF_QRY  + NROWS*HID)
#define OFF_SC1   (OFF_QHAT + NROWS*HID)
#define OFF_CAT   (OFF_SC1  + NROWS*NKEYS)
#define OFF_W2    (OFF_CAT  + NROWS*2*HID)
#define OFF_BF    (OFF_W2   + HID*HID)        // fused B: 512 x 256
#define OFF_B2    (OFF_BF   + 2*HID*HID)
#define OFF_BB    (OFF_B2   + HID)
#define SCRATCH_F (OFF_BB   + HID)

__device__ float g_scratch[SCRATCH_F];

// ---------------------------------------------------------------------------
// Tiled SGEMM device routine, 64x64 tile, BK=16, 256 threads, 4x4/thread,
// with register prefetch of the next K-tile (hides LDG latency).
//   AM=0: A is [M,K] row-major (use A[m][k]);  AM=1: A is [K,M] (use A[k][m])
//   BM=0: B is [K,N] row-major;               BM=1: B is [N,K]
// ---------------------------------------------------------------------------
template <int AM, int BM>
__device__ __forceinline__ void gemm_tile(
    const float* __restrict__ A, const float* __restrict__ B,
    const float* __restrict__ bias, float* __restrict__ C,
    int bm, int bn, int K, int lda, int ldb, int ldc,
    float (*As)[64], float (*Bs)[64])
{
    const int tid = threadIdx.x;
    const int tx  = tid & 15;   // 0..15
    const int ty  = tid >> 4;   // 0..15

    float  ra[4];  float4 ra4;
    float  rb[4];  float4 rb4;

    auto loadA = [&](int k0) {
        if constexpr (AM == 0) {
#pragma unroll
            for (int r = 0; r < 4; r++)
                ra[r] = A[(size_t)(bm + ty + 16 * r) * lda + k0 + tx];
        } else {
            ra4 = *reinterpret_cast<const float4*>(&A[(size_t)(k0 + ty) * lda + bm + tx * 4]);
        }
    };
    auto storeA = [&]() {
        if constexpr (AM == 0) {
#pragma unroll
            for (int r = 0; r < 4; r++) As[tx][ty + 16 * r] = ra[r];
        } else {
            As[ty][tx * 4 + 0] = ra4.x; As[ty][tx * 4 + 1] = ra4.y;
            As[ty][tx * 4 + 2] = ra4.z; As[ty][tx * 4 + 3] = ra4.w;
        }
    };
    auto loadB = [&](int k0) {
        if constexpr (BM == 1) {
#pragma unroll
            for (int r = 0; r < 4; r++)
                rb[r] = B[(size_t)(bn + ty + 16 * r) * ldb + k0 + tx];
        } else {
            rb4 = *reinterpret_cast<const float4*>(&B[(size_t)(k0 + ty) * ldb + bn + tx * 4]);
        }
    };
    auto storeB = [&]() {
        if constexpr (BM == 1) {
#pragma unroll
            for (int r = 0; r < 4; r++) Bs[tx][ty + 16 * r] = rb[r];
        } else {
            Bs[ty][tx * 4 + 0] = rb4.x; Bs[ty][tx * 4 + 1] = rb4.y;
            Bs[ty][tx * 4 + 2] = rb4.z; Bs[ty][tx * 4 + 3] = rb4.w;
        }
    };

    float acc[4][4] = {};
    loadA(0); loadB(0);

    for (int k0 = 0; k0 < K; k0 += 16) {
        storeA(); storeB();
        __syncthreads();
        if (k0 + 16 < K) { loadA(k0 + 16); loadB(k0 + 16); }
#pragma unroll
        for (int kk = 0; kk < 16; kk++) {
            float a[4], b[4];
#pragma unroll
            for (int i = 0; i < 4; i++) a[i] = As[kk][ty * 4 + i];
#pragma unroll
            for (int j = 0; j < 4; j++) b[j] = Bs[kk][tx * 4 + j];
#pragma unroll
            for (int i = 0; i < 4; i++)
#pragma unroll
                for (int j = 0; j < 4; j++)
                    acc[i][j] = fmaf(a[i], b[j], acc[i][j]);
        }
        __syncthreads();
    }

    float4 bb = make_float4(0.f, 0.f, 0.f, 0.f);
    if (bias) bb = *reinterpret_cast<const float4*>(&bias[bn + tx * 4]);

#pragma unroll
    for (int i = 0; i < 4; i++) {
        int m = bm + ty * 4 + i;
        float4 v;
        v.x = acc[i][0] + bb.x;  v.y = acc[i][1] + bb.y;
        v.z = acc[i][2] + bb.z;  v.w = acc[i][3] + bb.w;
        *reinterpret_cast<float4*>(&C[(size_t)m * ldc + bn + tx * 4]) = v;
    }
}

// ---------------------------------------------------------------------------
// Precompute: W2 = qq_w^T @ kq_w               (for qhat = h@W2 + b2)
//             Bfused[0:256]   = kq_w^T @ Pw_q^T (queue->out folded)
//             Bfused[256:512] = Pw_m^T          (transpose copy)
//             b2 = qq_b @ kq_w,  bf = proto_b + kq_b @ Pw_q^T
// grid (4, 13), 256 threads
// ---------------------------------------------------------------------------
__global__ void precompute_kernel(const float* __restrict__ qq_w,
                                  const float* __restrict__ qq_b,
                                  const float* __restrict__ kq_w,
                                  const float* __restrict__ kq_b,
                                  const float* __restrict__ proto_w,
                                  const float* __restrict__ proto_b,
                                  float* __restrict__ W2,
                                  float* __restrict__ Bfused,
                                  float* __restrict__ b2,
                                  float* __restrict__ bf)
{
    __shared__ __align__(16) float sbuf[64 * 65];  // big enough for both uses
    float (*As)[64] = (float(*)[64])sbuf;
    float (*Bs)[64] = (float(*)[64])(sbuf + 16 * 64);

    const int bx = blockIdx.x, by = blockIdx.y;
    const int bn = bx * 64;

    if (by < 4) {
        // W2[i][b] = sum_o qq_w[o][i] * kq_w[o][b]
        gemm_tile<1, 0>(qq_w, kq_w, nullptr, W2, by * 64, bn, HID, HID, HID, HID, As, Bs);
    } else if (by < 8) {
        // M[d][j] = sum_c kq_w[c][d] * proto_w[j][c]   (proto_w ld = 512)
        gemm_tile<1, 1>(kq_w, proto_w, nullptr, Bfused, (by - 4) * 64, bn, HID, HID, 2 * HID, HID, As, Bs);
    } else if (by < 12) {
        // transpose copy: Bfused[256+c][j] = proto_w[j][256+c]
        float (*tile)[65] = (float(*)[65])sbuf;
        const int c0 = (by - 8) * 64, j0 = bx * 64;
        const int tix = threadIdx.x & 63, tiy = threadIdx.x >> 6;
#pragma unroll
        for (int r = 0; r < 16; r++) {
            int jj = tiy + 4 * r;
            tile[jj][tix] = proto_w[(size_t)(j0 + jj) * (2 * HID) + HID + c0 + tix];
        }
        __syncthreads();
#pragma unroll
        for (int r = 0; r < 16; r++) {
            int cc = tiy + 4 * r;
            Bfused[(size_t)(HID + c0 + cc) * HID + j0 + tix] = tile[tix][cc];
        }
    } else if (bx == 0) {
        const int t = threadIdx.x;
        float s1 = 0.f;
        for (int o = 0; o < HID; o++) s1 = fmaf(qq_b[o], kq_w[o * HID + t], s1);
        b2[t] = s1;
        float s2 = proto_b[t];
        for (int c = 0; c < HID; c++) s2 = fmaf(kq_b[c], proto_w[(size_t)t * (2 * HID) + c], s2);
        bf[t] = s2;
    }
}

// ---------------------------------------------------------------------------
// Fused independent projections: KEY (960), QRY (1024), QHAT (1024)
// grid (4, 47): y<15 -> KEY, y<31 -> QRY, else QHAT
// ---------------------------------------------------------------------------
__global__ void proj_kernel(const float* __restrict__ memkey,
                            const float* __restrict__ h,
                            const float* __restrict__ key_w,  const float* __restrict__ key_b,
                            const float* __restrict__ query_w,const float* __restrict__ query_b,
                            const float* __restrict__ W2,     const float* __restrict__ b2,
                            float* __restrict__ KEY, float* __restrict__ QRY, float* __restrict__ QHAT)
{
    __shared__ float As[16][64];
    __shared__ float Bs[16][64];
    const int bn = blockIdx.x * 64;
    const int by = blockIdx.y;
    if (by < 15) {
        gemm_tile<0, 1>(memkey, key_w, key_b, KEY, by * 64, bn, HID, HID, HID, HID, As, Bs);
    } else if (by < 31) {
        gemm_tile<0, 1>(h, query_w, query_b, QRY, (by - 15) * 64, bn, HID, HID, HID, HID, As, Bs);
    } else {
        gemm_tile<0, 0>(h, W2, b2, QHAT, (by - 31) * 64, bn, HID, HID, HID, HID, As, Bs);
    }
}

// Level-1 scores: SC1 (1024 x 960) = QRY @ KEY^T, grid (15, 16)
__global__ void sc1_kernel(const float* __restrict__ QRY,
                           const float* __restrict__ KEY,
                           float* __restrict__ SC1)
{
    __shared__ float As[16][64];
    __shared__ float Bs[16][64];
    gemm_tile<0, 1>(QRY, KEY, nullptr, SC1, blockIdx.y * 64, blockIdx.x * 64,
                    HID, HID, HID, NKEYS, As, Bs);
}

// Final: out = CAT2(1024x512) @ Bfused(512x256) + bf, grid (4, 16)
__global__ void out_kernel(const float* __restrict__ CAT2,
                           const float* __restrict__ Bfused,
                           const float* __restrict__ bf,
                           float* __restrict__ out)
{
    __shared__ float As[16][64];
    __shared__ float Bs[16][64];
    gemm_tile<0, 0>(CAT2, Bfused, bf, out, blockIdx.y * 64, blockIdx.x * 64,
                    2 * HID, 2 * HID, HID, HID, As, Bs);
}

// ---------------------------------------------------------------------------
// Merged per-row kernel: level-1 top-5 + softmax + memory_z, then
// level-2 raw-candidate scoring + top-100 (bitonic threshold) + softmax +
// weighted raw sum. Writes CAT2[n] = [qsum | memz].
// One block (256 threads) per row.
// ---------------------------------------------------------------------------
__global__ void topk2_kernel(const float* __restrict__ scores,
                             const float* __restrict__ keyT,
                             const float* __restrict__ qhat,
                             const float* __restrict__ rawq,
                             float* __restrict__ cat)
{
    __shared__ float s[NKEYS];
    __shared__ float rv[256];
    __shared__ int   ri[256];
    __shared__ float w[TOPK];
    __shared__ int   idx[TOPK];
    __shared__ float qh[HID];
    __shared__ int   cls80[TOPK];
    __shared__ float sc[CAND];
    __shared__ float sb[512];
    __shared__ int   selrow[TOPKQ];
    __shared__ float selw[TOPKQ];
    __shared__ float s_den;
    __shared__ int   s_cnt;

    const int n = blockIdx.x, tid = threadIdx.x;

    qh[tid] = qhat[(size_t)n * HID + tid];
    if (tid == 0) s_cnt = 0;
    for (int i = tid; i < NKEYS; i += 256) s[i] = scores[(size_t)n * NKEYS + i];
    __syncthreads();

    // ---- level-1 top-5 (sequential argmax, lowest-index tiebreak) ----
    for (int j = 0; j < TOPK; j++) {
        float bv = -INFINITY; int bi = 0x7fffffff;
        for (int i = tid; i < NKEYS; i += 256) {
            float v = s[i];
            if (v > bv) { bv = v; bi = i; }
        }
        rv[tid] = bv; ri[tid] = bi;
        __syncthreads();
        for (int off = 128; off > 0; off >>= 1) {
            if (tid < off) {
                float ov = rv[tid + off]; int oi = ri[tid + off];
                if (ov > rv[tid] || (ov == rv[tid] && oi < ri[tid])) {
                    rv[tid] = ov; ri[tid] = oi;
                }
            }
            __syncthreads();
        }
        if (tid == 0) {
            idx[j] = ri[0];
            w[j]   = rv[0];
            s[ri[0]] = -INFINITY;
        }
        __syncthreads();
    }

    if (tid == 0) {
        float mx = w[0], den = 0.f;
#pragma unroll
        for (int j = 0; j < TOPK; j++) { w[j] = expf(w[j] - mx); den += w[j]; }
        float dinv = 1.f / den;
#pragma unroll
        for (int j = 0; j < TOPK; j++) {
            w[j] *= dinv;
            cls80[j] = (idx[j] / DCS) * CPB;
        }
    }
    __syncthreads();

    // memory_z -> CAT2 columns [256, 512)
    {
        float acc = 0.f;
#pragma unroll
        for (int j = 0; j < TOPK; j++)
            acc = fmaf(w[j], keyT[(size_t)idx[j] * HID + tid], acc);
        cat[(size_t)n * (2 * HID) + HID + tid] = acc;
    }

    // ---- level-2: scores against raw queue_key ----
#pragma unroll
    for (int mm = 0; mm < 2; mm++) {
        int m = tid + mm * 256;
        if (m < CAND) {
            int row = cls80[m / CPB] + (m % CPB);
            const float4* p  = reinterpret_cast<const float4*>(rawq + (size_t)row * HID);
            const float4* q4 = reinterpret_cast<const float4*>(qh);
            float a0 = 0.f, a1 = 0.f, a2 = 0.f, a3 = 0.f;
#pragma unroll
            for (int i = 0; i < HID / 4; i++) {
                float4 x = p[i], y = q4[i];
                a0 = fmaf(x.x, y.x, a0); a1 = fmaf(x.y, y.y, a1);
                a2 = fmaf(x.z, y.z, a2); a3 = fmaf(x.w, y.w, a3);
            }
            sc[m] = (a0 + a1) + (a2 + a3);
        }
    }
    __syncthreads();

    // ---- bitonic sort (ascending) of a value copy, padded to 512 ----
    sb[tid]       = sc[tid];
    sb[tid + 256] = (tid + 256 < CAND) ? sc[tid + 256] : -INFINITY;
    __syncthreads();
    for (int k = 2; k <= 512; k <<= 1) {
        for (int j = k >> 1; j > 0; j >>= 1) {
#pragma unroll
            for (int t = 0; t < 2; t++) {
                int i = tid + t * 256;
                int ixj = i ^ j;
                if (ixj > i) {
                    float a = sb[i], b = sb[ixj];
                    if ((a > b) == ((i & k) == 0)) { sb[i] = b; sb[ixj] = a; }
                }
            }
            __syncthreads();
        }
    }
    const float T  = sb[512 - TOPKQ];  // 100th-largest value
    const float mx = sb[511];          // max

    // ---- softmax denominator with exact-tie multiplicity ----
    {
        int cnt = 0; float den = 0.f;
#pragma unroll
        for (int mm = 0; mm < 2; mm++) {
            int m = tid + mm * 256;
            if (m < CAND && sc[m] > T) { cnt++; den += expf(sc[m] - mx); }
        }
        rv[tid] = den; ri[tid] = cnt;
    }
    __syncthreads();
    for (int off = 128; off > 0; off >>= 1) {
        if (tid < off) { rv[tid] += rv[tid + off]; ri[tid] += ri[tid + off]; }
        __syncthreads();
    }
    if (tid == 0) {
        int G = ri[0];
        s_den = rv[0] + (float)(TOPKQ - G) * expf(T - mx);
    }
    __syncthreads();
    const float dinv = 1.f / s_den;

    // ---- selection list: all > T, then fill with == T up to 100 ----
#pragma unroll
    for (int mm = 0; mm < 2; mm++) {
        int m = tid + mm * 256;
        if (m < CAND && sc[m] > T) {
            int p = atomicAdd(&s_cnt, 1);
            selrow[p] = cls80[m / CPB] + (m % CPB);
            selw[p]   = expf(sc[m] - mx) * dinv;
        }
    }
    __syncthreads();
#pragma unroll
    for (int mm = 0; mm < 2; mm++) {
        int m = tid + mm * 256;
        if (m < CAND && sc[m] == T) {
            int p = atomicAdd(&s_cnt, 1);
            if (p < TOPKQ) {
                selrow[p] = cls80[m / CPB] + (m % CPB);
                selw[p]   = expf(T - mx) * dinv;
            }
        }
    }
    __syncthreads();

    // ---- weighted sum of selected raw rows -> CAT2 columns [0, 256) ----
    float acc0 = 0.f, acc1 = 0.f, acc2 = 0.f, acc3 = 0.f;
    for (int p = 0; p < TOPKQ; p += 4) {
        acc0 = fmaf(selw[p + 0], rawq[(size_t)selrow[p + 0] * HID + tid], acc0);
        acc1 = fmaf(selw[p + 1], rawq[(size_t)selrow[p + 1] * HID + tid], acc1);
        acc2 = fmaf(selw[p + 2], rawq[(size_t)selrow[p + 2] * HID + tid], acc2);
        acc3 = fmaf(selw[p + 3], rawq[(size_t)selrow[p + 3] * HID + tid], acc3);
    }
    cat[(size_t)n * (2 * HID) + tid] = (acc0 + acc1) + (acc2 + acc3);
}

// ---------------------------------------------------------------------------
// Host launcher
// ---------------------------------------------------------------------------
extern "C" void kernel_launch(void* const* d_in, const int* in_sizes, int n_in,
                              void* d_out, int out_size)
{
    const int sh = (n_in >= 15) ? 0 : 1;
    const float* h          = (const float*)d_in[0];
    const float* memory_key = (const float*)d_in[3 - sh];
    const float* queue_key  = (const float*)d_in[4 - sh];
    const float* key_w      = (const float*)d_in[5 - sh];
    const float* key_b      = (const float*)d_in[6 - sh];
    const float* query_w    = (const float*)d_in[7 - sh];
    const float* query_b    = (const float*)d_in[8 - sh];
    const float* kq_w       = (const float*)d_in[9 - sh];
    const float* kq_b       = (const float*)d_in[10 - sh];
    const float* qq_w       = (const float*)d_in[11 - sh];
    const float* qq_b       = (const float*)d_in[12 - sh];
    const float* proto_w    = (const float*)d_in[13 - sh];
    const float* proto_b    = (const float*)d_in[14 - sh];
    float* out = (float*)d_out;

    void* sp = nullptr;  cudaGetSymbolAddress(&sp, g_scratch);
    float* S     = (float*)sp;
    float* KEY   = S + OFF_KEY;
    float* QRY   = S + OFF_QRY;
    float* QHAT  = S + OFF_QHAT;
    float* SC1   = S + OFF_SC1;
    float* CAT2  = S + OFF_CAT;
    float* W2    = S + OFF_W2;
    float* BFUSE = S + OFF_BF;
    float* B2    = S + OFF_B2;
    float* BB    = S + OFF_BB;

    // 1) tiny weight-space precompute (W2, fused output B, biases)
    precompute_kernel<<<dim3(4, 13), 256>>>(qq_w, qq_b, kq_w, kq_b,
                                            proto_w, proto_b, W2, BFUSE, B2, BB);
    // 2) all projections in one wave (KEY, QRY, QHAT)
    proj_kernel<<<dim3(4, 47), 256>>>(memory_key, h, key_w, key_b,
                                      query_w, query_b, W2, B2, KEY, QRY, QHAT);
    // 3) level-1 scores
    sc1_kernel<<<dim3(15, 16), 256>>>(QRY, KEY, SC1);
    // 4) merged top-k levels -> CAT2 = [qsum | memz]
    topk2_kernel<<<NROWS, 256>>>(SC1, KEY, QHAT, queue_key, CAT2);
    // 5) fused output GEMM
    out_kernel<<<dim3(4, 16), 256>>>(CAT2, BFUSE, BB, out);
}

// round 4
// speedup vs baseline: 1.8929x; 1.7057x over previous
#include <cuda_runtime.h>
#include <math.h>

#define HID    256
#define BS     64
#define DCS    16
#define NCLS   60
#define QSZ    5
#define TOPK   5
#define TOPKQ  100
#define NROWS  (BS * DCS)          // 1024
#define NKEYS  (NCLS * DCS)        // 960
#define CAND   (TOPK * QSZ * DCS)  // 400
#define CPB    (QSZ * DCS)         // 80
#define CAP    (NROWS * TOPK)      // 5120 max pairs per class

// ---------------------------------------------------------------------------
// Scratch (float):
#define OFF_KEY   0
#define OFF_QRY   (OFF_KEY  + NKEYS*HID)
#define OFF_QQ    (OFF_QRY  + NROWS*HID)
#define OFF_QHAT  (OFF_QQ   + NROWS*HID)
#define OFF_KEYP  (OFF_QHAT + NROWS*HID)
#define OFF_SC1   (OFF_KEYP + NKEYS*HID)
#define OFF_SC2   (OFF_SC1  + NROWS*NKEYS)
#define OFF_WFL   (OFF_SC2  + NROWS*CAND)
#define OFF_OUTM  (OFF_WFL  + NROWS*CAND)
#define OFF_PART  (OFF_OUTM + NROWS*HID)
#define OFF_BFQ   (OFF_PART + NROWS*TOPK*HID)
#define OFF_BF    (OFF_BFQ  + HID*HID)
#define SCRATCH_F (OFF_BF   + HID)

__device__ float g_scratch[SCRATCH_F];
__device__ int   g_pairs[NCLS * CAP];
__device__ int   g_cnt[NCLS];

// ---------------------------------------------------------------------------
// SGEMM core v2: 64x64 tile, BK=32, 256 threads, 4x4/thread, reg prefetch,
// vectorized LDS. AM=0: A[M,K]; AM=1: A[K,M]. BM=0: B[K,N]; BM=1: B[N,K].
// ---------------------------------------------------------------------------
#define SROW 68   // padded smem row (multiple of 4 for float4 alignment)

template <int AM, int BM>
__device__ __forceinline__ void gemm_tile2(
    const float* __restrict__ A, const float* __restrict__ B,
    const float* __restrict__ bias, float* __restrict__ C,
    int bm, int bn, int K, int lda, int ldb, int ldc, float* sbuf)
{
    float* As = sbuf;
    float* Bs = sbuf + 32 * SROW;
    const int tid = threadIdx.x;
    const int tx = tid & 15, ty = tid >> 4;

    float4 ra0, ra1, rb0, rb1;

    auto ldA = [&](int k0) {
        if constexpr (AM == 0) {
            int r = tid >> 3, c = (tid & 7) * 4;
            ra0 = *(const float4*)(A + (size_t)(bm + r)      * lda + k0 + c);
            ra1 = *(const float4*)(A + (size_t)(bm + r + 32) * lda + k0 + c);
        } else {
            int k = tid >> 4, c = (tid & 15) * 4;
            ra0 = *(const float4*)(A + (size_t)(k0 + k)      * lda + bm + c);
            ra1 = *(const float4*)(A + (size_t)(k0 + k + 16) * lda + bm + c);
        }
    };
    auto stA = [&]() {
        if constexpr (AM == 0) {
            int r = tid >> 3, c = (tid & 7) * 4;
            As[(c+0)*SROW + r] = ra0.x; As[(c+1)*SROW + r] = ra0.y;
            As[(c+2)*SROW + r] = ra0.z; As[(c+3)*SROW + r] = ra0.w;
            As[(c+0)*SROW + r+32] = ra1.x; As[(c+1)*SROW + r+32] = ra1.y;
            As[(c+2)*SROW + r+32] = ra1.z; As[(c+3)*SROW + r+32] = ra1.w;
        } else {
            int k = tid >> 4, c = (tid & 15) * 4;
            *(float4*)(As + k*SROW + c)      = ra0;
            *(float4*)(As + (k+16)*SROW + c) = ra1;
        }
    };
    auto ldB = [&](int k0) {
        if constexpr (BM == 1) {
            int r = tid >> 3, c = (tid & 7) * 4;
            rb0 = *(const float4*)(B + (size_t)(bn + r)      * ldb + k0 + c);
            rb1 = *(const float4*)(B + (size_t)(bn + r + 32) * ldb + k0 + c);
        } else {
            int k = tid >> 4, c = (tid & 15) * 4;
            rb0 = *(const float4*)(B + (size_t)(k0 + k)      * ldb + bn + c);
            rb1 = *(const float4*)(B + (size_t)(k0 + k + 16) * ldb + bn + c);
        }
    };
    auto stB = [&]() {
        if constexpr (BM == 1) {
            int r = tid >> 3, c = (tid & 7) * 4;
            Bs[(c+0)*SROW + r] = rb0.x; Bs[(c+1)*SROW + r] = rb0.y;
            Bs[(c+2)*SROW + r] = rb0.z; Bs[(c+3)*SROW + r] = rb0.w;
            Bs[(c+0)*SROW + r+32] = rb1.x; Bs[(c+1)*SROW + r+32] = rb1.y;
            Bs[(c+2)*SROW + r+32] = rb1.z; Bs[(c+3)*SROW + r+32] = rb1.w;
        } else {
            int k = tid >> 4, c = (tid & 15) * 4;
            *(float4*)(Bs + k*SROW + c)      = rb0;
            *(float4*)(Bs + (k+16)*SROW + c) = rb1;
        }
    };

    float acc[4][4] = {};
    ldA(0); ldB(0);
    for (int k0 = 0; k0 < K; k0 += 32) {
        stA(); stB();
        __syncthreads();
        if (k0 + 32 < K) { ldA(k0 + 32); ldB(k0 + 32); }
#pragma unroll
        for (int kk = 0; kk < 32; kk++) {
            float4 a = *(float4*)(As + kk*SROW + ty*4);
            float4 b = *(float4*)(Bs + kk*SROW + tx*4);
            acc[0][0] = fmaf(a.x, b.x, acc[0][0]); acc[0][1] = fmaf(a.x, b.y, acc[0][1]);
            acc[0][2] = fmaf(a.x, b.z, acc[0][2]); acc[0][3] = fmaf(a.x, b.w, acc[0][3]);
            acc[1][0] = fmaf(a.y, b.x, acc[1][0]); acc[1][1] = fmaf(a.y, b.y, acc[1][1]);
            acc[1][2] = fmaf(a.y, b.z, acc[1][2]); acc[1][3] = fmaf(a.y, b.w, acc[1][3]);
            acc[2][0] = fmaf(a.z, b.x, acc[2][0]); acc[2][1] = fmaf(a.z, b.y, acc[2][1]);
            acc[2][2] = fmaf(a.z, b.z, acc[2][2]); acc[2][3] = fmaf(a.z, b.w, acc[2][3]);
            acc[3][0] = fmaf(a.w, b.x, acc[3][0]); acc[3][1] = fmaf(a.w, b.y, acc[3][1]);
            acc[3][2] = fmaf(a.w, b.z, acc[3][2]); acc[3][3] = fmaf(a.w, b.w, acc[3][3]);
        }
        __syncthreads();
    }

    float4 bb = make_float4(0.f, 0.f, 0.f, 0.f);
    if (bias) bb = *(const float4*)(bias + bn + tx * 4);
#pragma unroll
    for (int i = 0; i < 4; i++) {
        int m = bm + ty * 4 + i;
        float4 v;
        v.x = acc[i][0] + bb.x; v.y = acc[i][1] + bb.y;
        v.z = acc[i][2] + bb.z; v.w = acc[i][3] + bb.w;
        *(float4*)(C + (size_t)m * ldc + bn + tx * 4) = v;
    }
}

// ---------------------------------------------------------------------------
// K1: KEY(15), QRY(16), QQ(16), BfQ(4x4), bias/cnt.  grid (4, 52)
// ---------------------------------------------------------------------------
__global__ __launch_bounds__(256)
void k1_proj(const float* __restrict__ memkey, const float* __restrict__ h,
             const float* __restrict__ key_w,  const float* __restrict__ key_b,
             const float* __restrict__ query_w,const float* __restrict__ query_b,
             const float* __restrict__ qq_w,   const float* __restrict__ qq_b,
             const float* __restrict__ kq_w,   const float* __restrict__ kq_b,
             const float* __restrict__ proto_w,const float* __restrict__ proto_b,
             float* __restrict__ KEY, float* __restrict__ QRY, float* __restrict__ QQ,
             float* __restrict__ BFQ, float* __restrict__ BF)
{
    __shared__ __align__(16) float sbuf[2 * 32 * SROW];
    const int bn = blockIdx.x * 64, by = blockIdx.y;
    if (by < 15) {
        gemm_tile2<0,1>(memkey, key_w, key_b, KEY, by*64, bn, HID, HID, HID, HID, sbuf);
    } else if (by < 31) {
        gemm_tile2<0,1>(h, query_w, query_b, QRY, (by-15)*64, bn, HID, HID, HID, HID, sbuf);
    } else if (by < 47) {
        gemm_tile2<0,1>(h, qq_w, qq_b, QQ, (by-31)*64, bn, HID, HID, HID, HID, sbuf);
    } else if (by < 51) {
        // BfQ[d][j] = sum_c kq_w[c][d] * proto_w[j][c]   (proto_w ld=512)
        gemm_tile2<1,1>(kq_w, proto_w, nullptr, BFQ, (by-47)*64, bn, HID, HID, 2*HID, HID, sbuf);
    } else if (blockIdx.x == 0) {
        const int t = threadIdx.x;
        float s2 = proto_b[t];
        for (int c = 0; c < HID; c++)
            s2 = fmaf(kq_b[c], proto_w[(size_t)t * (2*HID) + c], s2);
        BF[t] = s2;
        if (t < NCLS) g_cnt[t] = 0;
    }
}

// ---------------------------------------------------------------------------
// K2: SC1 (15x16), QHAT (4x16), KEYP (4x15).  grid (23, 16)
// ---------------------------------------------------------------------------
__global__ __launch_bounds__(256)
void k2_score1(const float* __restrict__ QRY, const float* __restrict__ KEY,
               const float* __restrict__ QQ,  const float* __restrict__ kq_w,
               const float* __restrict__ proto_w,
               float* __restrict__ SC1, float* __restrict__ QHAT, float* __restrict__ KEYP)
{
    __shared__ __align__(16) float sbuf[2 * 32 * SROW];
    const int bx = blockIdx.x, by = blockIdx.y;
    if (bx < 15) {
        gemm_tile2<0,1>(QRY, KEY, nullptr, SC1, by*64, bx*64, HID, HID, HID, NKEYS, sbuf);
    } else if (bx < 19) {
        gemm_tile2<0,0>(QQ, kq_w, nullptr, QHAT, by*64, (bx-15)*64, HID, HID, HID, HID, sbuf);
    } else if (by < 15) {
        // KEYP = KEY @ Pw_m^T   (proto_w columns [256,512), ld=512)
        gemm_tile2<0,1>(KEY, proto_w + HID, nullptr, KEYP, by*64, (bx-19)*64, HID, HID, 2*HID, HID, sbuf);
    }
}

// ---------------------------------------------------------------------------
// K3: per-row top-5 of 960 (single-pass merge), softmax, OUTM, pair lists.
// ---------------------------------------------------------------------------
__global__ __launch_bounds__(256)
void k3_topk1(const float* __restrict__ SC1, const float* __restrict__ KEYP,
              float* __restrict__ OUTM)
{
    __shared__ float sv[256 * TOPK];
    __shared__ int   si[256 * TOPK];
    __shared__ float sw[TOPK];
    __shared__ int   sidx[TOPK];

    const int n = blockIdx.x, tid = threadIdx.x;

    float lv[TOPK]; int li[TOPK];
#pragma unroll
    for (int j = 0; j < TOPK; j++) { lv[j] = -INFINITY; li[j] = 0x7fffffff; }

    const float* row = SC1 + (size_t)n * NKEYS;
    for (int i = tid; i < NKEYS; i += 256) {
        float v = row[i];
        if (v > lv[TOPK-1]) {
            int p = TOPK - 1;
            while (p > 0 && v > lv[p-1]) { lv[p] = lv[p-1]; li[p] = li[p-1]; p--; }
            lv[p] = v; li[p] = i;
        }
    }
#pragma unroll
    for (int j = 0; j < TOPK; j++) { sv[tid*TOPK + j] = lv[j]; si[tid*TOPK + j] = li[j]; }
    __syncthreads();

    for (int off = 128; off > 0; off >>= 1) {
        if (tid < off) {
            float av[TOPK], bv2[TOPK], ov[TOPK];
            int   ai[TOPK], bi2[TOPK], oi[TOPK];
#pragma unroll
            for (int j = 0; j < TOPK; j++) {
                av[j] = sv[tid*TOPK + j];        ai[j] = si[tid*TOPK + j];
                bv2[j] = sv[(tid+off)*TOPK + j]; bi2[j] = si[(tid+off)*TOPK + j];
            }
            int pa = 0, pb = 0;
#pragma unroll
            for (int j = 0; j < TOPK; j++) {
                bool ta = (av[pa] > bv2[pb]) || (av[pa] == bv2[pb] && ai[pa] < bi2[pb]);
                if (ta) { ov[j] = av[pa]; oi[j] = ai[pa]; pa++; }
                else    { ov[j] = bv2[pb]; oi[j] = bi2[pb]; pb++; }
            }
#pragma unroll
            for (int j = 0; j < TOPK; j++) { sv[tid*TOPK + j] = ov[j]; si[tid*TOPK + j] = oi[j]; }
        }
        __syncthreads();
    }

    if (tid == 0) {
        float w[TOPK];
        float mx = sv[0], den = 0.f;
#pragma unroll
        for (int j = 0; j < TOPK; j++) { w[j] = expf(sv[j] - mx); den += w[j]; }
        float dinv = 1.f / den;
#pragma unroll
        for (int j = 0; j < TOPK; j++) {
            int idx = si[j];
            sw[j] = w[j] * dinv;
            sidx[j] = idx;
            int c = idx / DCS;
            int p = atomicAdd(&g_cnt[c], 1);
            g_pairs[c * CAP + p] = n * 8 + j;
        }
    }
    __syncthreads();

    float acc = 0.f;
#pragma unroll
    for (int j = 0; j < TOPK; j++)
        acc = fmaf(sw[j], KEYP[(size_t)sidx[j] * HID + tid], acc);
    OUTM[(size_t)n * HID + tid] = acc;
}

// ---------------------------------------------------------------------------
// K4: class-batched scoring GEMM. 32 pairs x 80 cand, K=256 in chunks of 32.
// grid (60, 20); each block loops 8 m-tiles strided by 20.
// ---------------------------------------------------------------------------
__global__ __launch_bounds__(256)
void k4_score2(const float* __restrict__ QHAT, const float* __restrict__ rawq,
               float* __restrict__ SC2)
{
    __shared__ float As[32][33];   // [k][m]
    __shared__ float Bsh[32][81];  // [k][q]
    __shared__ int   spn[32], spj[32];

    const int c = blockIdx.x, tid = threadIdx.x;
    const int cnt = g_cnt[c];
    const int tm = tid >> 4, tn = tid & 15;
    const float* rbase = rawq + (size_t)c * CPB * HID;

    for (int tt = blockIdx.y; tt * 32 < cnt; tt += 20) {
        const int m0 = tt * 32;
        __syncthreads();
        if (tid < 32) {
            int mi = m0 + tid;
            int pm = g_pairs[c * CAP + (mi < cnt ? mi : m0)];
            spn[tid] = pm >> 3; spj[tid] = pm & 7;
        }
        __syncthreads();
        const int rA = spn[tid >> 3];   // row for A-loads (m = tid>>3)

        float acc[2][5] = {};
        for (int k0 = 0; k0 < HID; k0 += 32) {
            __syncthreads();
            {   // A: 32 pairs x 32 k
                int m = tid >> 3, c4 = (tid & 7) * 4;
                float4 v = *(const float4*)(QHAT + (size_t)rA * HID + k0 + c4);
                As[c4+0][m] = v.x; As[c4+1][m] = v.y; As[c4+2][m] = v.z; As[c4+3][m] = v.w;
            }
            {   // B: 80 rows x 32 k
#pragma unroll
                for (int p = 0; p < 3; p++) {
                    int idx = tid + p * 256;
                    if (idx < CPB * 8) {
                        int q = idx >> 3, c4 = (idx & 7) * 4;
                        float4 v = *(const float4*)(rbase + (size_t)q * HID + k0 + c4);
                        Bsh[c4+0][q] = v.x; Bsh[c4+1][q] = v.y;
                        Bsh[c4+2][q] = v.z; Bsh[c4+3][q] = v.w;
                    }
                }
            }
            __syncthreads();
#pragma unroll
            for (int kk = 0; kk < 32; kk++) {
                float a0 = As[kk][tm*2 + 0], a1 = As[kk][tm*2 + 1];
                float b0 = Bsh[kk][tn*5+0], b1 = Bsh[kk][tn*5+1], b2 = Bsh[kk][tn*5+2];
                float b3 = Bsh[kk][tn*5+3], b4 = Bsh[kk][tn*5+4];
                acc[0][0] = fmaf(a0,b0,acc[0][0]); acc[0][1] = fmaf(a0,b1,acc[0][1]);
                acc[0][2] = fmaf(a0,b2,acc[0][2]); acc[0][3] = fmaf(a0,b3,acc[0][3]);
                acc[0][4] = fmaf(a0,b4,acc[0][4]);
                acc[1][0] = fmaf(a1,b0,acc[1][0]); acc[1][1] = fmaf(a1,b1,acc[1][1]);
                acc[1][2] = fmaf(a1,b2,acc[1][2]); acc[1][3] = fmaf(a1,b3,acc[1][3]);
                acc[1][4] = fmaf(a1,b4,acc[1][4]);
            }
        }
#pragma unroll
        for (int i = 0; i < 2; i++) {
            int m = tm * 2 + i;
            if (m0 + m < cnt) {
                int n = spn[m], j = spj[m];
                float* dst = SC2 + (size_t)n * CAND + j * CPB + tn * 5;
#pragma unroll
                for (int jq = 0; jq < 5; jq++) dst[jq] = acc[i][jq];
            }
        }
    }
}

// ---------------------------------------------------------------------------
// K5: per-row top-100 threshold + softmax weights -> dense WFL[n][400]
// ---------------------------------------------------------------------------
__global__ __launch_bounds__(256)
void k5_select(const float* __restrict__ SC2, float* __restrict__ WFL)
{
    __shared__ float sc[CAND];
    __shared__ float sb[512];
    __shared__ float rr[256];
    __shared__ int   ii[256];
    __shared__ int   ta[512], tb[512];
    __shared__ float s_den;
    __shared__ int   s_G;

    const int n = blockIdx.x, tid = threadIdx.x;

    sc[tid] = SC2[(size_t)n * CAND + tid];
    if (tid < CAND - 256) sc[tid + 256] = SC2[(size_t)n * CAND + tid + 256];
    __syncthreads();

    sb[tid] = sc[tid];
    sb[tid + 256] = (tid < CAND - 256) ? sc[tid + 256] : -INFINITY;
    __syncthreads();
    for (int k = 2; k <= 512; k <<= 1) {
        for (int j = k >> 1; j > 0; j >>= 1) {
#pragma unroll
            for (int t = 0; t < 2; t++) {
                int i = tid + t * 256;
                int ixj = i ^ j;
                if (ixj > i) {
                    float a = sb[i], b = sb[ixj];
                    if ((a > b) == ((i & k) == 0)) { sb[i] = b; sb[ixj] = a; }
                }
            }
            __syncthreads();
        }
    }
    const float T  = sb[512 - TOPKQ];
    const float mx = sb[511];

    {   // strict-greater count + partial den
        int cnt = 0; float den = 0.f;
        float v = sc[tid];
        if (v > T) { cnt++; den += expf(v - mx); }
        if (tid < CAND - 256) {
            float v2 = sc[tid + 256];
            if (v2 > T) { cnt++; den += expf(v2 - mx); }
        }
        rr[tid] = den; ii[tid] = cnt;
    }
    __syncthreads();
    for (int off = 128; off > 0; off >>= 1) {
        if (tid < off) { rr[tid] += rr[tid + off]; ii[tid] += ii[tid + off]; }
        __syncthreads();
    }
    if (tid == 0) {
        s_G = ii[0];
        s_den = rr[0] + (float)(TOPKQ - ii[0]) * expf(T - mx);
    }
    __syncthreads();
    const int   G = s_G;
    const float dinv = 1.f / s_den;

    // inclusive scan of tie flags (index order), Hillis-Steele ping-pong
    ta[tid]       = (sc[tid] == T) ? 1 : 0;
    ta[tid + 256] = (tid < CAND - 256 && sc[tid + 256] == T) ? 1 : 0;
    __syncthreads();
    int* src = ta; int* dst = tb;
    for (int d = 1; d < 512; d <<= 1) {
        dst[tid]       = src[tid]       + (tid >= d ? src[tid - d] : 0);
        dst[tid + 256] = src[tid + 256] + (tid + 256 >= d ? src[tid + 256 - d] : 0);
        __syncthreads();
        int* t = src; src = dst; dst = t;
    }

    const float wT = expf(T - mx) * dinv;
#pragma unroll
    for (int t = 0; t < 2; t++) {
        int m = tid + t * 256;
        if (m < CAND) {
            float v = sc[m], w = 0.f;
            if (v > T) w = expf(v - mx) * dinv;
            else if (v == T) { if (src[m] - 1 < TOPKQ - G) w = wT; }
            WFL[(size_t)n * CAND + m] = w;
        }
    }
}

// ---------------------------------------------------------------------------
// K6: class-batched weighted-sum GEMM: PART[(n*5+j)][d] = W(80) . raw(80 x d)
// tile: 32 pairs x 64 dims, K=80 fully staged. grid (60, 20, 4), loop 8.
// ---------------------------------------------------------------------------
__global__ __launch_bounds__(256)
void k6_wsum(const float* __restrict__ WFL, const float* __restrict__ rawq,
             float* __restrict__ PART)
{
    __shared__ float Aw[32][81];    // [m][q]
    __shared__ float Bsh[CPB][64];  // [q][d]
    __shared__ int   spn[32], spj[32];

    const int c = blockIdx.x, tid = threadIdx.x;
    const int cnt = g_cnt[c];
    if (blockIdx.y * 32 >= cnt) return;
    const int d0 = blockIdx.z * 64;
    const int tm = tid >> 4, tn = tid & 15;
    const float* rbase = rawq + (size_t)c * CPB * HID;

    {   // B: 80 rows x 64 dims (class-invariant across m-tiles)
#pragma unroll
        for (int p = 0; p < 5; p++) {
            int idx = tid + p * 256;   // 80*16 = 1280 slots
            int q = idx >> 4, c4 = (idx & 15) * 4;
            *(float4*)&Bsh[q][c4] = *(const float4*)(rbase + (size_t)q * HID + d0 + c4);
        }
    }

    for (int tt = blockIdx.y; tt * 32 < cnt; tt += 20) {
        const int m0 = tt * 32;
        __syncthreads();
        if (tid < 32) {
            int mi = m0 + tid;
            int pm = g_pairs[c * CAP + (mi < cnt ? mi : m0)];
            spn[tid] = pm >> 3; spj[tid] = pm & 7;
        }
        __syncthreads();
        {   // A: weights, 32 pairs x 80
#pragma unroll
            for (int p = 0; p < 3; p++) {
                int idx = tid + p * 256;   // 32*20 = 640 slots
                if (idx < 640) {
                    int m = idx / 20, c4 = (idx % 20) * 4;
                    float4 v = *(const float4*)(WFL + (size_t)spn[m] * CAND + spj[m] * CPB + c4);
                    Aw[m][c4+0] = v.x; Aw[m][c4+1] = v.y; Aw[m][c4+2] = v.z; Aw[m][c4+3] = v.w;
                }
            }
        }
        __syncthreads();

        float acc[2][4] = {};
#pragma unroll 4
        for (int q = 0; q < CPB; q++) {
            float a0 = Aw[tm*2 + 0][q], a1 = Aw[tm*2 + 1][q];
            float4 b = *(float4*)&Bsh[q][tn*4];
            acc[0][0] = fmaf(a0,b.x,acc[0][0]); acc[0][1] = fmaf(a0,b.y,acc[0][1]);
            acc[0][2] = fmaf(a0,b.z,acc[0][2]); acc[0][3] = fmaf(a0,b.w,acc[0][3]);
            acc[1][0] = fmaf(a1,b.x,acc[1][0]); acc[1][1] = fmaf(a1,b.y,acc[1][1]);
            acc[1][2] = fmaf(a1,b.z,acc[1][2]); acc[1][3] = fmaf(a1,b.w,acc[1][3]);
        }
#pragma unroll
        for (int i = 0; i < 2; i++) {
            int m = tm * 2 + i;
            if (m0 + m < cnt) {
                float4 v = make_float4(acc[i][0], acc[i][1], acc[i][2], acc[i][3]);
                *(float4*)(PART + (size_t)(spn[m] * TOPK + spj[m]) * HID + d0 + tn * 4) = v;
            }
        }
    }
}

// ---------------------------------------------------------------------------
// K7: out = (sum_j PART[m*5+j]) @ BfQ + OUTM + bf.  tile 64m x 32n, grid (8,16)
// ---------------------------------------------------------------------------
__global__ __launch_bounds__(256)
void k7_out(const float* __restrict__ PART, const float* __restrict__ BFQ,
            const float* __restrict__ OUTM, const float* __restrict__ BF,
            float* __restrict__ out)
{
    __shared__ float As[32][65];   // [k][m]
    __shared__ float Bsh[32][36];  // [k][n]
    const int tid = threadIdx.x;
    const int bm = blockIdx.y * 64, bn = blockIdx.x * 32;
    const int ty = tid >> 3, tx = tid & 7;   // ty: 32 m-groups(x2), tx: 8 n-groups(x4)

    float acc[2][4] = {};
    for (int k0 = 0; k0 < HID; k0 += 32) {
        __syncthreads();
        {   // A: sum of 5 PART rows; 64 m x 32 k
            int r = tid >> 3, c4 = (tid & 7) * 4;
#pragma unroll
            for (int h = 0; h < 2; h++) {
                int m = bm + r + h * 32;
                float4 s = make_float4(0.f, 0.f, 0.f, 0.f);
#pragma unroll
                for (int j = 0; j < TOPK; j++) {
                    float4 v = *(const float4*)(PART + (size_t)(m * TOPK + j) * HID + k0 + c4);
                    s.x += v.x; s.y += v.y; s.z += v.z; s.w += v.w;
                }
                As[c4+0][r + h*32] = s.x; As[c4+1][r + h*32] = s.y;
                As[c4+2][r + h*32] = s.z; As[c4+3][r + h*32] = s.w;
            }
        }
        {   // B: BfQ [K=256][N=256] row-major; 32 k x 32 n
            int k = tid >> 3, c4 = (tid & 7) * 4;
            *(float4*)&Bsh[k][c4] = *(const float4*)(BFQ + (size_t)(k0 + k) * HID + bn + c4);
        }
        __syncthreads();
#pragma unroll
        for (int kk = 0; kk < 32; kk++) {
            float a0 = As[kk][ty*2 + 0], a1 = As[kk][ty*2 + 1];
            float4 b = *(float4*)&Bsh[kk][tx*4];
            acc[0][0] = fmaf(a0,b.x,acc[0][0]); acc[0][1] = fmaf(a0,b.y,acc[0][1]);
            acc[0][2] = fmaf(a0,b.z,acc[0][2]); acc[0][3] = fmaf(a0,b.w,acc[0][3]);
            acc[1][0] = fmaf(a1,b.x,acc[1][0]); acc[1][1] = fmaf(a1,b.y,acc[1][1]);
            acc[1][2] = fmaf(a1,b.z,acc[1][2]); acc[1][3] = fmaf(a1,b.w,acc[1][3]);
        }
    }

    float4 bb = *(const float4*)(BF + bn + tx * 4);
#pragma unroll
    for (int i = 0; i < 2; i++) {
        int m = bm + ty * 2 + i;
        float4 om = *(const float4*)(OUTM + (size_t)m * HID + bn + tx * 4);
        float4 v;
        v.x = acc[i][0] + bb.x + om.x; v.y = acc[i][1] + bb.y + om.y;
        v.z = acc[i][2] + bb.z + om.z; v.w = acc[i][3] + bb.w + om.w;
        *(float4*)(out + (size_t)m * HID + bn + tx * 4) = v;
    }
}

// ---------------------------------------------------------------------------
extern "C" void kernel_launch(void* const* d_in, const int* in_sizes, int n_in,
                              void* d_out, int out_size)
{
    const int sh = (n_in >= 15) ? 0 : 1;
    const float* h          = (const float*)d_in[0];
    const float* memory_key = (const float*)d_in[3 - sh];
    const float* queue_key  = (const float*)d_in[4 - sh];
    const float* key_w      = (const float*)d_in[5 - sh];
    const float* key_b      = (const float*)d_in[6 - sh];
    const float* query_w    = (const float*)d_in[7 - sh];
    const float* query_b    = (const float*)d_in[8 - sh];
    const float* kq_w       = (const float*)d_in[9 - sh];
    const float* kq_b       = (const float*)d_in[10 - sh];
    const float* qq_w       = (const float*)d_in[11 - sh];
    const float* qq_b       = (const float*)d_in[12 - sh];
    const float* proto_w    = (const float*)d_in[13 - sh];
    const float* proto_b    = (const float*)d_in[14 - sh];
    float* out = (float*)d_out;

    void* sp = nullptr; cudaGetSymbolAddress(&sp, g_scratch);
    float* S = (float*)sp;
    float* KEY  = S + OFF_KEY;
    float* QRY  = S + OFF_QRY;
    float* QQ   = S + OFF_QQ;
    float* QHAT = S + OFF_QHAT;
    float* KEYP = S + OFF_KEYP;
    float* SC1  = S + OFF_SC1;
    float* SC2  = S + OFF_SC2;
    float* WFL  = S + OFF_WFL;
    float* OUTM = S + OFF_OUTM;
    float* PART = S + OFF_PART;
    float* BFQ  = S + OFF_BFQ;
    float* BF   = S + OFF_BF;

    k1_proj<<<dim3(4, 52), 256>>>(memory_key, h, key_w, key_b, query_w, query_b,
                                  qq_w, qq_b, kq_w, kq_b, proto_w, proto_b,
                                  KEY, QRY, QQ, BFQ, BF);
    k2_score1<<<dim3(23, 16), 256>>>(QRY, KEY, QQ, kq_w, proto_w, SC1, QHAT, KEYP);
    k3_topk1<<<NROWS, 256>>>(SC1, KEYP, OUTM);
    k4_score2<<<dim3(60, 20), 256>>>(QHAT, queue_key, SC2);
    k5_select<<<NROWS, 256>>>(SC2, WFL);
    k6_wsum<<<dim3(60, 20, 4), 256>>>(WFL, queue_key, PART);
    k7_out<<<dim3(8, 16), 256>>>(PART, BFQ, OUTM, BF, out);
}